// round 2
// baseline (speedup 1.0000x reference)
#include <cuda_runtime.h>
#include <math.h>

#define D_DIM 3072
#define C_DIM 10
#define B_DIM 4096
#define R_ROWS 4
#define WARPS 8
#define BLOCK (WARPS * 32)
#define GRID (B_DIM / (R_ROWS * WARPS))   // 128 blocks

#define EPS_REG 0.1f
#define NUM_STAB 1e-6f

// scratch (no cudaMalloc allowed)
__device__ __align__(16) float g_Wt[C_DIM * D_DIM];   // W transposed [C][D]
__device__ float g_M[C_DIM * C_DIM];                  // M = W^T W
__device__ float g_partials[GRID];

// ---------------------------------------------------------------------------
// Prep: transpose W into g_Wt and compute M = W^T W.
// grid = 100 blocks (one M entry each), block = 128 threads.
// ---------------------------------------------------------------------------
__global__ void prep_kernel(const float* __restrict__ W) {
    const int pair = blockIdx.x;            // 0..99
    const int j1 = pair / C_DIM;
    const int j2 = pair % C_DIM;

    float partial = 0.f;
    for (int d = threadIdx.x; d < D_DIM; d += 128)
        partial += W[d * C_DIM + j1] * W[d * C_DIM + j2];

    // cooperative transpose (grid-stride over 30720 elements)
    for (int idx = blockIdx.x * 128 + threadIdx.x; idx < C_DIM * D_DIM; idx += 100 * 128) {
        int j = idx / D_DIM;
        int d = idx - j * D_DIM;
        g_Wt[idx] = W[d * C_DIM + j];
    }

    // reduce partial (fixed order -> deterministic)
    #pragma unroll
    for (int off = 16; off; off >>= 1)
        partial += __shfl_xor_sync(0xffffffffu, partial, off);

    __shared__ float sw[4];
    int lane = threadIdx.x & 31, w = threadIdx.x >> 5;
    if (lane == 0) sw[w] = partial;
    __syncthreads();
    if (threadIdx.x == 0)
        g_M[pair] = (sw[0] + sw[1]) + (sw[2] + sw[3]);
}

// ---------------------------------------------------------------------------
// Main: z = data @ W (warp handles 4 rows), analytic epilogue, block partial.
// ---------------------------------------------------------------------------
__global__ __launch_bounds__(BLOCK) void main_kernel(const float* __restrict__ data) {
    __shared__ float sM[C_DIM * C_DIM];
    __shared__ float sWarpSum[WARPS];
    if (threadIdx.x < C_DIM * C_DIM) sM[threadIdx.x] = g_M[threadIdx.x];
    __syncthreads();

    const int warpId = threadIdx.x >> 5;
    const int lane   = threadIdx.x & 31;
    const int row0   = (blockIdx.x * WARPS + warpId) * R_ROWS;

    float acc[R_ROWS][C_DIM];
    #pragma unroll
    for (int r = 0; r < R_ROWS; r++)
        #pragma unroll
        for (int j = 0; j < C_DIM; j++) acc[r][j] = 0.f;

    const int NITER = D_DIM / 128;   // 24; lane covers 4 floats per iter
    #pragma unroll 2
    for (int iter = 0; iter < NITER; iter++) {
        const int d0 = iter * 128 + lane * 4;
        float4 x[R_ROWS];
        #pragma unroll
        for (int r = 0; r < R_ROWS; r++)
            x[r] = __ldcs(reinterpret_cast<const float4*>(
                       data + (size_t)(row0 + r) * D_DIM + d0));
        #pragma unroll
        for (int j = 0; j < C_DIM; j++) {
            float4 w = *reinterpret_cast<const float4*>(g_Wt + j * D_DIM + d0);
            #pragma unroll
            for (int r = 0; r < R_ROWS; r++) {
                acc[r][j] = fmaf(x[r].x, w.x, acc[r][j]);
                acc[r][j] = fmaf(x[r].y, w.y, acc[r][j]);
                acc[r][j] = fmaf(x[r].z, w.z, acc[r][j]);
                acc[r][j] = fmaf(x[r].w, w.w, acc[r][j]);
            }
        }
    }

    // butterfly reduce all 40 accumulators across the warp
    #pragma unroll
    for (int r = 0; r < R_ROWS; r++)
        #pragma unroll
        for (int j = 0; j < C_DIM; j++)
            #pragma unroll
            for (int off = 16; off; off >>= 1)
                acc[r][j] += __shfl_xor_sync(0xffffffffu, acc[r][j], off);

    // lanes 0..3: analytic epilogue for one row each
    float reg = 0.f;
    if (lane < R_ROWS) {
        const float ALPHA = 1.0f - (float)C_DIM * NUM_STAB;
        float z[C_DIM];
        #pragma unroll
        for (int j = 0; j < C_DIM; j++) z[j] = acc[lane][j];

        float zmax = z[0];
        #pragma unroll
        for (int j = 1; j < C_DIM; j++) zmax = fmaxf(zmax, z[j]);

        float e[C_DIM], S = 0.f;
        #pragma unroll
        for (int j = 0; j < C_DIM; j++) { e[j] = expf(z[j] - zmax); S += e[j]; }
        const float invS = 1.f / S;

        float sig[C_DIM], p[C_DIM], s[C_DIM];
        float ssum = 0.f, psum_m = 0.f;
        #pragma unroll
        for (int j = 0; j < C_DIM; j++) {
            sig[j] = e[j] * invS;
            p[j]   = fmaf(ALPHA, sig[j], NUM_STAB);
            s[j]   = sqrtf(p[j]);
            ssum  += s[j];
            if (j < C_DIM - 1) psum_m += p[j];
        }
        const float sL = s[C_DIM - 1];
        const float t  = 1.f / (1.f - sL);

        float arg = ssum * 0.31622776601683794f;     // 1/sqrt(10)
        arg = fminf(1.f, fmaxf(-1.f, arg));
        const float delta = 2.f * acosf(arg);
        const float rho   = (2.f * (1.f - sL) - psum_m) * t;

        // v = M sigma, q = sigma^T M sigma
        float v[C_DIM], q = 0.f;
        #pragma unroll
        for (int k = 0; k < C_DIM; k++) {
            float a = 0.f;
            #pragma unroll
            for (int j = 0; j < C_DIM; j++)
                a = fmaf(sM[k * C_DIM + j], sig[j], a);
            v[k] = a;
            q = fmaf(sig[k], a, q);
        }

        // ||J||_F^2 = sum_i g_i^T M g_i with
        //   g_i = a_i e_i + b_i e_L - (a_i+b_i) sigma
        const float gL = ALPHA * sig[C_DIM - 1] / sL;   // alpha*sig_L/s_L
        float fro = 0.f;
        #pragma unroll
        for (int i = 0; i < C_DIM - 1; i++) {
            float a = t * ALPHA * sig[i] / s[i];
            float b = s[i] * t * t * gL;
            float c = a + b;
            fro += a * a * sM[i * C_DIM + i]
                 + b * b * sM[C_DIM * C_DIM - 1]
                 + c * c * q
                 + 2.f * a * b * sM[i * C_DIM + (C_DIM - 1)]
                 - 2.f * c * (a * v[i] + b * v[C_DIM - 1]);
        }
        const float jac_norm = sqrtf(fmaxf(fro, 0.f));

        const float xv = jac_norm - delta / (rho * EPS_REG);
        reg = (xv > 0.f) ? xv : (expf(xv) - 1.f);
    }

    // deterministic in-block reduction
    #pragma unroll
    for (int off = 16; off; off >>= 1)
        reg += __shfl_xor_sync(0xffffffffu, reg, off);
    if (lane == 0) sWarpSum[warpId] = reg;
    __syncthreads();
    if (threadIdx.x == 0) {
        float ssum = 0.f;
        #pragma unroll
        for (int w = 0; w < WARPS; w++) ssum += sWarpSum[w];
        g_partials[blockIdx.x] = ssum;
    }
}

// ---------------------------------------------------------------------------
// Final: fixed-order sum of 128 block partials -> mean
// ---------------------------------------------------------------------------
__global__ void final_kernel(float* __restrict__ out) {
    float v = g_partials[threadIdx.x];   // exactly 128 threads, GRID==128
    #pragma unroll
    for (int off = 16; off; off >>= 1)
        v += __shfl_xor_sync(0xffffffffu, v, off);
    __shared__ float sw[4];
    int lane = threadIdx.x & 31, w = threadIdx.x >> 5;
    if (lane == 0) sw[w] = v;
    __syncthreads();
    if (threadIdx.x == 0)
        out[0] = ((sw[0] + sw[1]) + (sw[2] + sw[3])) * (1.0f / (float)B_DIM);
}

extern "C" void kernel_launch(void* const* d_in, const int* in_sizes, int n_in,
                              void* d_out, int out_size) {
    const float* data = (const float*)d_in[0];   // [4096, 3072] f32
    const float* W    = (const float*)d_in[1];   // [3072, 10]   f32
    float* out        = (float*)d_out;           // scalar f32

    prep_kernel<<<100, 128>>>(W);
    main_kernel<<<GRID, BLOCK>>>(data);
    final_kernel<<<1, 128>>>(out);
}

// round 3
// speedup vs baseline: 1.5602x; 1.5602x over previous
#include <cuda_runtime.h>
#include <math.h>

#define D_DIM 3072
#define C_DIM 10
#define B_DIM 4096
#define R_ROWS 4
#define HALVES 2
#define D_HALF (D_DIM / HALVES)            // 1536
#define WARPS 8
#define BLOCK (WARPS * 32)                 // 256
#define PAIRS (WARPS / 2)                  // 4 row-tiles per block
#define GRIDM (B_DIM / (R_ROWS * PAIRS))   // 256 blocks

#define EPS_REG 0.1f
#define NUM_STAB 1e-6f

// scratch (no cudaMalloc allowed)
__device__ __align__(16) float g_Wt[C_DIM * D_DIM];   // W transposed [C][D]
__device__ float g_M[C_DIM * C_DIM];                  // M = W^T W
__device__ float g_partials[GRIDM];
__device__ unsigned int g_count = 0;                  // reset by last block each call

// ---- packed fp32x2 helpers (sm_103a FFMA2 path) ----
__device__ __forceinline__ unsigned long long ffma2(unsigned long long a,
                                                    unsigned long long b,
                                                    unsigned long long c) {
    unsigned long long d;
    asm("fma.rn.f32x2 %0, %1, %2, %3;" : "=l"(d) : "l"(a), "l"(b), "l"(c));
    return d;
}
__device__ __forceinline__ unsigned long long pk2(float a, float b) {
    unsigned long long r;
    asm("mov.b64 %0, {%1, %2};" : "=l"(r) : "f"(a), "f"(b));
    return r;
}
__device__ __forceinline__ float unpk_sum(unsigned long long v) {
    float lo, hi;
    asm("mov.b64 {%0, %1}, %2;" : "=f"(lo), "=f"(hi) : "l"(v));
    return lo + hi;
}

// ---------------------------------------------------------------------------
// Prep: blocks 0..99 compute one M entry each (256 threads); first 120 blocks
// also transpose W into g_Wt (one shot, coalesced enough for 122 KB).
// ---------------------------------------------------------------------------
__global__ __launch_bounds__(256) void prep_kernel(const float* __restrict__ W) {
    // transpose slice
    {
        int idx = blockIdx.x * 256 + threadIdx.x;
        if (idx < C_DIM * D_DIM) {
            int j = idx / D_DIM;
            int d = idx - j * D_DIM;
            g_Wt[idx] = W[d * C_DIM + j];
        }
    }
    if (blockIdx.x >= C_DIM * C_DIM) return;

    const int j1 = blockIdx.x / C_DIM;
    const int j2 = blockIdx.x % C_DIM;

    float partial = 0.f;
    #pragma unroll 4
    for (int d = threadIdx.x; d < D_DIM; d += 256)
        partial = fmaf(W[d * C_DIM + j1], W[d * C_DIM + j2], partial);

    #pragma unroll
    for (int off = 16; off; off >>= 1)
        partial += __shfl_xor_sync(0xffffffffu, partial, off);

    __shared__ float sw[8];
    int lane = threadIdx.x & 31, w = threadIdx.x >> 5;
    if (lane == 0) sw[w] = partial;
    __syncthreads();
    if (threadIdx.x == 0) {
        float s = 0.f;
        #pragma unroll
        for (int k = 0; k < 8; k++) s += sw[k];
        g_M[blockIdx.x] = s;
    }
}

// ---------------------------------------------------------------------------
// Main: warp = (row-tile of 4, D-half). FFMA2 inner loop. Halves combined via
// smem; analytic Jacobian epilogue; fused deterministic final reduction.
// ---------------------------------------------------------------------------
__global__ __launch_bounds__(BLOCK, 2) void main_kernel(const float* __restrict__ data,
                                                        float* __restrict__ out) {
    __shared__ float sM[C_DIM * C_DIM];
    __shared__ float sAcc[WARPS][R_ROWS * C_DIM];
    __shared__ float sWarpSum[WARPS];
    __shared__ bool  sIsLast;
    if (threadIdx.x < C_DIM * C_DIM) sM[threadIdx.x] = g_M[threadIdx.x];

    const int warpId = threadIdx.x >> 5;
    const int lane   = threadIdx.x & 31;
    const int pairId = warpId >> 1;
    const int half   = warpId & 1;
    const int row0   = (blockIdx.x * PAIRS + pairId) * R_ROWS;

    const float* xbase = data + (size_t)row0 * D_DIM + half * D_HALF + lane * 4;
    const float* wbase = g_Wt + half * D_HALF + lane * 4;

    unsigned long long acc2[R_ROWS][C_DIM];
    #pragma unroll
    for (int r = 0; r < R_ROWS; r++)
        #pragma unroll
        for (int j = 0; j < C_DIM; j++) acc2[r][j] = 0ULL;

    const int NIT = D_HALF / 128;   // 12
    for (int it = 0; it < NIT; it++) {
        unsigned long long xl[R_ROWS], xh[R_ROWS];
        #pragma unroll
        for (int r = 0; r < R_ROWS; r++) {
            float4 xf = __ldcs(reinterpret_cast<const float4*>(
                            xbase + (size_t)r * D_DIM + it * 128));
            xl[r] = pk2(xf.x, xf.y);
            xh[r] = pk2(xf.z, xf.w);
        }
        #pragma unroll
        for (int j = 0; j < C_DIM; j++) {
            float4 wf = *reinterpret_cast<const float4*>(wbase + j * D_DIM + it * 128);
            unsigned long long wl = pk2(wf.x, wf.y);
            unsigned long long wh = pk2(wf.z, wf.w);
            #pragma unroll
            for (int r = 0; r < R_ROWS; r++)
                acc2[r][j] = ffma2(xh[r], wh, ffma2(xl[r], wl, acc2[r][j]));
        }
    }

    // horizontal add + full-warp butterfly reduce (40 values)
    float acc[R_ROWS][C_DIM];
    #pragma unroll
    for (int r = 0; r < R_ROWS; r++)
        #pragma unroll
        for (int j = 0; j < C_DIM; j++) {
            float v = unpk_sum(acc2[r][j]);
            #pragma unroll
            for (int off = 16; off; off >>= 1)
                v += __shfl_xor_sync(0xffffffffu, v, off);
            acc[r][j] = v;
        }

    // combine the two D-halves of each row-tile (odd warp -> even warp)
    if (half == 1 && lane == 0) {
        #pragma unroll
        for (int r = 0; r < R_ROWS; r++)
            #pragma unroll
            for (int j = 0; j < C_DIM; j++)
                sAcc[warpId][r * C_DIM + j] = acc[r][j];
    }
    __syncthreads();

    float reg = 0.f;
    if (half == 0) {
        #pragma unroll
        for (int r = 0; r < R_ROWS; r++)
            #pragma unroll
            for (int j = 0; j < C_DIM; j++)
                acc[r][j] += sAcc[warpId + 1][r * C_DIM + j];

        if (lane < R_ROWS) {
            const float ALPHA = 1.0f - (float)C_DIM * NUM_STAB;
            float z[C_DIM];
            #pragma unroll
            for (int j = 0; j < C_DIM; j++) z[j] = acc[lane][j];

            float zmax = z[0];
            #pragma unroll
            for (int j = 1; j < C_DIM; j++) zmax = fmaxf(zmax, z[j]);

            float e[C_DIM], S = 0.f;
            #pragma unroll
            for (int j = 0; j < C_DIM; j++) { e[j] = expf(z[j] - zmax); S += e[j]; }
            const float invS = 1.f / S;

            float sig[C_DIM], p[C_DIM], s[C_DIM];
            float ssum = 0.f, psum_m = 0.f;
            #pragma unroll
            for (int j = 0; j < C_DIM; j++) {
                sig[j] = e[j] * invS;
                p[j]   = fmaf(ALPHA, sig[j], NUM_STAB);
                s[j]   = sqrtf(p[j]);
                ssum  += s[j];
                if (j < C_DIM - 1) psum_m += p[j];
            }
            const float sL = s[C_DIM - 1];
            const float t  = 1.f / (1.f - sL);

            float arg = ssum * 0.31622776601683794f;     // 1/sqrt(10)
            arg = fminf(1.f, fmaxf(-1.f, arg));
            const float delta = 2.f * acosf(arg);
            const float rho   = (2.f * (1.f - sL) - psum_m) * t;

            // v = M sigma, q = sigma^T M sigma
            float v[C_DIM], q = 0.f;
            #pragma unroll
            for (int k = 0; k < C_DIM; k++) {
                float a = 0.f;
                #pragma unroll
                for (int j = 0; j < C_DIM; j++)
                    a = fmaf(sM[k * C_DIM + j], sig[j], a);
                v[k] = a;
                q = fmaf(sig[k], a, q);
            }

            // ||J||_F^2 = sum_i g_i^T M g_i,  g_i = a_i e_i + b_i e_L - (a_i+b_i) sigma
            const float gL = ALPHA * sig[C_DIM - 1] / sL;
            float fro = 0.f;
            #pragma unroll
            for (int i = 0; i < C_DIM - 1; i++) {
                float a = t * ALPHA * sig[i] / s[i];
                float b = s[i] * t * t * gL;
                float c = a + b;
                fro += a * a * sM[i * C_DIM + i]
                     + b * b * sM[C_DIM * C_DIM - 1]
                     + c * c * q
                     + 2.f * a * b * sM[i * C_DIM + (C_DIM - 1)]
                     - 2.f * c * (a * v[i] + b * v[C_DIM - 1]);
            }
            const float jac_norm = sqrtf(fmaxf(fro, 0.f));

            const float xv = jac_norm - delta / (rho * EPS_REG);
            reg = (xv > 0.f) ? xv : (expf(xv) - 1.f);
        }
    }

    // deterministic block reduction
    #pragma unroll
    for (int off = 16; off; off >>= 1)
        reg += __shfl_xor_sync(0xffffffffu, reg, off);
    if (lane == 0) sWarpSum[warpId] = reg;
    __syncthreads();
    if (threadIdx.x == 0) {
        float ssum = 0.f;
        #pragma unroll
        for (int w = 0; w < WARPS; w++) ssum += sWarpSum[w];
        g_partials[blockIdx.x] = ssum;
        __threadfence();
        sIsLast = (atomicAdd(&g_count, 1u) == GRIDM - 1);
    }
    __syncthreads();

    // fused final reduction: last block sums all 256 partials in fixed order
    if (sIsLast) {
        __threadfence();
        float v = g_partials[threadIdx.x];        // BLOCK == GRIDM == 256
        #pragma unroll
        for (int off = 16; off; off >>= 1)
            v += __shfl_xor_sync(0xffffffffu, v, off);
        if (lane == 0) sWarpSum[warpId] = v;
        __syncthreads();
        if (threadIdx.x == 0) {
            float ssum = 0.f;
            #pragma unroll
            for (int w = 0; w < WARPS; w++) ssum += sWarpSum[w];
            out[0] = ssum * (1.0f / (float)B_DIM);
            g_count = 0;                           // reset for next graph replay
        }
    }
}

extern "C" void kernel_launch(void* const* d_in, const int* in_sizes, int n_in,
                              void* d_out, int out_size) {
    const float* data = (const float*)d_in[0];   // [4096, 3072] f32
    const float* W    = (const float*)d_in[1];   // [3072, 10]   f32
    float* out        = (float*)d_out;           // scalar f32

    prep_kernel<<<240, 256>>>(W);
    main_kernel<<<GRIDM, BLOCK>>>(data, out);
}